// round 9
// baseline (speedup 1.0000x reference)
#include <cuda_runtime.h>
#include <cuda_fp16.h>

// Problem constants (fixed by the dataset)
#define NN  100000     // nodes
#define EE  1600000    // edges
#define HH  4          // heads
#define DD  32         // dim per head
#define HD  128        // H*D
#define EFD 32         // edge feat dim
#define ETN 8          // edge types
#define NEG_SLOPE 0.2f

#define NBLK   ((NN + 7) / 8)                 // node blocks: 8 warps = 8 nodes
#define BUCKET 64                             // per-node edge capacity
// dst degrees ~ Poisson(16); P(any node > 64) ~ 5e-14 on this fixed dataset.

// Scratch (device globals — zero-initialized at module load; no allocation)
__device__ uint2    g_fsh[(size_t)NN * 32];  // fs in fp16, [node][h][d], 4 halves/lane
__device__ float    g_el[(size_t)NN * HH];
__device__ float    g_er[(size_t)NN * HH];
__device__ float    g_ee[ETN * HH];
__device__ int      g_cnt[NN];               // per-dst degree/cursor (reset by dst_kernel)
__device__ uint2    g_edges[(size_t)NN * BUCKET]; // {edge id, src|(etype<<24)} per-node bucket

// ---------------------------------------------------------------------------
// Kernel 0 (fused prep), 256 threads/block:
//   blocks [0, NBLK): node pass, one warp per node, float4 loads.
//     lane l owns dims [4l, 4l+4) = head (l>>3), dims 4*(l&7)..+3.
//     fsh halves land exactly in dst_kernel's uint2-lane layout.
//   last block:       ee[t,h] (32 threads)
// ---------------------------------------------------------------------------
__global__ void prep_kernel(const float* __restrict__ feat,
                            const float* __restrict__ fc,
                            const float* __restrict__ attn_l,
                            const float* __restrict__ attn_r,
                            const int*   __restrict__ ntype,
                            const float* __restrict__ edge_emb,
                            const float* __restrict__ W_e,
                            const float* __restrict__ attn_e) {
    int blk = blockIdx.x;
    int tid = threadIdx.x;            // 0..255

    if (blk < NBLK) {
        int node = blk * 8 + (tid >> 5);
        if (node >= NN) return;
        int lane = tid & 31;

        int ty = ntype[node];
        float4 f = *(const float4*)(feat + (size_t)node * HD + lane * 4);
        float4 c = *(const float4*)(fc   + (size_t)ty   * HD + lane * 4);
        float4 v;
        v.x = f.x * c.x; v.y = f.y * c.y; v.z = f.z * c.z; v.w = f.w * c.w;

        __half2 h0 = __floats2half2_rn(v.x, v.y);
        __half2 h1 = __floats2half2_rn(v.z, v.w);
        uint2 pack;
        pack.x = *(unsigned*)&h0;
        pack.y = *(unsigned*)&h1;
        g_fsh[(size_t)node * 32 + lane] = pack;

        float4 al = *(const float4*)(attn_l + lane * 4);
        float4 ar = *(const float4*)(attn_r + lane * 4);
        float pl = v.x * al.x + v.y * al.y + v.z * al.z + v.w * al.w;
        float pr = v.x * ar.x + v.y * ar.y + v.z * ar.z + v.w * ar.w;
        // reduce within each 8-lane head group
        #pragma unroll
        for (int o = 4; o > 0; o >>= 1) {
            pl += __shfl_xor_sync(0xffffffffu, pl, o);
            pr += __shfl_xor_sync(0xffffffffu, pr, o);
        }
        if ((lane & 7) == 0) {
            int h = lane >> 3;
            g_el[node * HH + h] = pl;
            g_er[node * HH + h] = pr;
        }
    } else {
        if (tid < 32) {
            int et = tid >> 2;
            int h  = tid & 3;
            const float* em = edge_emb + et * EFD;
            float acc = 0.0f;
            for (int f = 0; f < EFD; f++) {
                const float* w = W_e + (h * EFD + f) * EFD;
                float dot = 0.0f;
                #pragma unroll 8
                for (int k = 0; k < EFD; k++) dot += em[k] * w[k];
                acc += dot * attn_e[h * EFD + f];
            }
            g_ee[et * HH + h] = acc;
        }
    }
}

// ---------------------------------------------------------------------------
// Kernel 1: bucket scatter. 4 edges per thread via int4 loads. Each edge
// claims a slot in its dst node's 64-entry bucket. No hist, no scan.
// ---------------------------------------------------------------------------
__device__ __forceinline__ void scatter_one(int e, int s, int d, int t) {
    int pos = atomicAdd(&g_cnt[d], 1);
    if (pos < BUCKET)
        g_edges[(size_t)d * BUCKET + pos] =
            make_uint2((unsigned)e, (unsigned)s | ((unsigned)t << 24));
}

__global__ void scatter_kernel(const int* __restrict__ src,
                               const int* __restrict__ dst,
                               const int* __restrict__ efeat) {
    int e0 = (blockIdx.x * blockDim.x + threadIdx.x) * 4;
    if (e0 + 3 < EE) {
        int4 s4 = *(const int4*)(src   + e0);
        int4 d4 = *(const int4*)(dst   + e0);
        int4 t4 = *(const int4*)(efeat + e0);
        scatter_one(e0 + 0, s4.x, d4.x, t4.x);
        scatter_one(e0 + 1, s4.y, d4.y, t4.y);
        scatter_one(e0 + 2, s4.z, d4.z, t4.z);
        scatter_one(e0 + 3, s4.w, d4.w, t4.w);
    } else {
        for (int e = e0; e < EE; e++)
            scatter_one(e, src[e], dst[e], efeat[e]);
    }
}

// ---------------------------------------------------------------------------
// Kernel 2: one warp per dst node. Fused: score -> exp -> segment sum ->
// normalized attention (a_out) -> weighted fp16 fs[src] aggregation ->
// residual -> coalesced store. No atomics on output. Fast path for deg <= 32
// keeps ex in registers (most nodes: mean degree 16). Resets g_cnt.
// Lane layout for aggregation: lane l owns head (l>>3), dims 4*(l&7)..+3.
// ---------------------------------------------------------------------------
__global__ void __launch_bounds__(256, 5)
dst_kernel(const float* __restrict__ feat,
           float* __restrict__ rst,
           float* __restrict__ a_out) {
    __shared__ float sh_ex[8][128];            // per-warp staged ex (32 edges x 4 heads)

    int w    = (blockIdx.x * blockDim.x + threadIdx.x) >> 5;  // node id
    int wloc = threadIdx.x >> 5;
    int lane = threadIdx.x & 31;
    if (w >= NN) return;

    int deg   = g_cnt[w];
    if (deg > BUCKET) deg = BUCKET;            // never happens; memory safety
    int start = w * BUCKET;
    int end   = start + deg;
    if (lane == 0) g_cnt[w] = 0;               // reset for next pipeline call

    int hsel = lane >> 3;                      // head owned for aggregation

    float4 er4 = *(const float4*)(g_er + (size_t)w * HH);

    float4 sacc = make_float4(0.f, 0.f, 0.f, 0.f);
    float a0 = 0.f, a1 = 0.f, a2 = 0.f, a3 = 0.f;

    // saved for the single-chunk fast path (deg <= 32)
    float4 ex_save = make_float4(0.f, 0.f, 0.f, 0.f);
    int    e_save  = -1;

    for (int base = 0; base < deg; base += 32) {
        int n = deg - base; if (n > 32) n = 32;

        float4 ex = make_float4(0.f, 0.f, 0.f, 0.f);
        int e = -1;
        unsigned pk = 0;

        if (lane < n) {
            int idx = start + base + lane;
            uint2 ed = g_edges[idx];
            e  = (int)ed.x;
            pk = ed.y;
            int sidx = (int)(pk & 0xFFFFFFu);
            int t    = (int)(pk >> 24);

            float4 el4 = *(const float4*)(g_el + (size_t)sidx * HH);
            float4 ee4 = *(const float4*)(g_ee + t * HH);

            float x0 = el4.x + er4.x + ee4.x;
            float x1 = el4.y + er4.y + ee4.y;
            float x2 = el4.z + er4.z + ee4.z;
            float x3 = el4.w + er4.w + ee4.w;
            x0 = (x0 > 0.f) ? x0 : NEG_SLOPE * x0;
            x1 = (x1 > 0.f) ? x1 : NEG_SLOPE * x1;
            x2 = (x2 > 0.f) ? x2 : NEG_SLOPE * x2;
            x3 = (x3 > 0.f) ? x3 : NEG_SLOPE * x3;
            ex.x = __expf(x0);
            ex.y = __expf(x1);
            ex.z = __expf(x2);
            ex.w = __expf(x3);

            sacc.x += ex.x; sacc.y += ex.y; sacc.z += ex.z; sacc.w += ex.w;

            *(float4*)(&sh_ex[wloc][lane * 4]) = ex;

            if (deg > 32) {
                // staging: will be normalized in a second sweep
                *(float4*)(a_out + (size_t)e * HH) = ex;
            }
        }
        __syncwarp();
        ex_save = ex;
        e_save  = e;

        int sidx_l = (int)(pk & 0xFFFFFFu);
        const float* exrow = &sh_ex[wloc][hsel];
        #pragma unroll 8
        for (int j = 0; j < n; j++) {
            float c  = exrow[j * 4];                       // ex_j[my head]
            int   sj = __shfl_sync(0xffffffffu, sidx_l, j);
            uint2 v  = g_fsh[(size_t)sj * 32 + lane];      // 4 halves: my head, my 4 dims
            float2 p0 = __half22float2(*(__half2*)&v.x);
            float2 p1 = __half22float2(*(__half2*)&v.y);
            a0 += c * p0.x;
            a1 += c * p0.y;
            a2 += c * p1.x;
            a3 += c * p1.y;
        }
        __syncwarp();
    }

    // reduce softmax denominators across the warp
    #pragma unroll
    for (int o = 16; o > 0; o >>= 1) {
        sacc.x += __shfl_xor_sync(0xffffffffu, sacc.x, o);
        sacc.y += __shfl_xor_sync(0xffffffffu, sacc.y, o);
        sacc.z += __shfl_xor_sync(0xffffffffu, sacc.z, o);
        sacc.w += __shfl_xor_sync(0xffffffffu, sacc.w, o);
    }
    float4 inv;
    inv.x = (sacc.x != 0.f) ? 1.f / sacc.x : 0.f;
    inv.y = (sacc.y != 0.f) ? 1.f / sacc.y : 0.f;
    inv.z = (sacc.z != 0.f) ? 1.f / sacc.z : 0.f;
    inv.w = (sacc.w != 0.f) ? 1.f / sacc.w : 0.f;

    // write normalized attention
    if (deg <= 32) {
        if (e_save >= 0) {
            float4 av;
            av.x = ex_save.x * inv.x;
            av.y = ex_save.y * inv.y;
            av.z = ex_save.z * inv.z;
            av.w = ex_save.w * inv.w;
            *(float4*)(a_out + (size_t)e_save * HH) = av;
        }
    } else {
        for (int i = start + lane; i < end; i += 32) {
            int e = (int)g_edges[i].x;
            float4 v = *(float4*)(a_out + (size_t)e * HH);
            v.x *= inv.x; v.y *= inv.y; v.z *= inv.z; v.w *= inv.w;
            *(float4*)(a_out + (size_t)e * HH) = v;
        }
    }

    // my head's inverse denominator
    float invh = (hsel == 0) ? inv.x : (hsel == 1) ? inv.y : (hsel == 2) ? inv.z : inv.w;

    // residual + output: lane l writes float4 at node*128 + l*4 (coalesced)
    size_t b = (size_t)w * HD + lane * 4;
    float4 fv = *(const float4*)(feat + b);
    float4 ov;
    ov.x = fv.x + a0 * invh;
    ov.y = fv.y + a1 * invh;
    ov.z = fv.z + a2 * invh;
    ov.w = fv.w + a3 * invh;
    *(float4*)(rst + b) = ov;
}

// ---------------------------------------------------------------------------
extern "C" void kernel_launch(void* const* d_in, const int* in_sizes, int n_in,
                              void* d_out, int out_size) {
    const float* feat     = (const float*)d_in[0];
    const float* fc       = (const float*)d_in[1];
    const float* edge_emb = (const float*)d_in[2];
    const float* W_e      = (const float*)d_in[3];
    const float* attn_l   = (const float*)d_in[4];
    const float* attn_r   = (const float*)d_in[5];
    const float* attn_e   = (const float*)d_in[6];
    const int*   ntype    = (const int*)d_in[7];
    const int*   efeat    = (const int*)d_in[8];
    const int*   src      = (const int*)d_in[9];
    const int*   dst      = (const int*)d_in[10];

    float* rst   = (float*)d_out;                       // [N, H, D]
    float* a_out = (float*)d_out + (size_t)NN * HD;     // [E, H, 1]

    prep_kernel<<<NBLK + 1, 256>>>(feat, fc, attn_l, attn_r, ntype,
                                   edge_emb, W_e, attn_e);
    {
        int threads = 256;                    // 4 edges per thread
        int blocks = (EE / 4 + threads - 1) / threads;
        scatter_kernel<<<blocks, threads>>>(src, dst, efeat);
    }
    {
        int threads = 256;                    // 8 warps = 8 nodes per block
        int blocks = (NN + 8 - 1) / 8;
        dst_kernel<<<blocks, threads>>>(feat, rst, a_out);
    }
}

// round 10
// speedup vs baseline: 1.5575x; 1.5575x over previous
#include <cuda_runtime.h>
#include <cuda_fp16.h>

// Problem constants (fixed by the dataset)
#define NN  100000     // nodes
#define EE  1600000    // edges
#define HH  4          // heads
#define DD  32         // dim per head
#define HD  128        // H*D
#define EFD 32         // edge feat dim
#define ETN 8          // edge types
#define NEG_SLOPE 0.2f

#define SCAN_T 256
#define SCAN_B ((NN + SCAN_T - 1) / SCAN_T)   // 391
#define NBLK4  ((NN + 31) / 32)               // node blocks: 8 warps x 4 nodes
#define HBLK2  ((EE + 1023) / 1024)           // hist blocks: 256 thr x 4 edges

// Scratch (device globals — zero-initialized at module load; no allocation)
__device__ uint2    g_fsh[(size_t)NN * 32];  // fs in fp16, [node][h][d], 4 halves/lane
__device__ float    g_el[(size_t)NN * HH];
__device__ float    g_er[(size_t)NN * HH];
__device__ float    g_ee[ETN * HH];
__device__ int      g_cnt[NN];               // per-dst degree (zeroed by scan_kernel)
__device__ int      g_off[NN];               // CSR start offsets
__device__ int      g_cur[NN];               // scatter cursors -> CSR end offsets
__device__ int      g_total;                 // CSR allocation counter
__device__ uint2    g_edges[EE];             // {edge id, src|(etype<<24)} in CSR order

// ---------------------------------------------------------------------------
// Kernel 0 (fused prep), 256 threads/block:
//   blocks [0, NBLK4):   node pass, one warp per 4 NODES, batched float4
//     loads (MLP=4 per thread). lane l owns dims [4l,4l+4) = head (l>>3).
//     fsh halves land exactly in dst_kernel's uint2-lane layout.
//   blocks [NBLK4, NBLK4+HBLK2): dst histogram (4 edges/thread via int4)
//   last block:          ee[t,h] (32 threads) + reset g_total
// ---------------------------------------------------------------------------
__global__ void prep_kernel(const float* __restrict__ feat,
                            const float* __restrict__ fc,
                            const float* __restrict__ attn_l,
                            const float* __restrict__ attn_r,
                            const int*   __restrict__ ntype,
                            const int*   __restrict__ dst,
                            const float* __restrict__ edge_emb,
                            const float* __restrict__ W_e,
                            const float* __restrict__ attn_e) {
    int blk = blockIdx.x;
    int tid = threadIdx.x;            // 0..255

    if (blk < NBLK4) {
        int lane = tid & 31;
        int base = blk * 32 + (tid >> 5) * 4;   // first of this warp's 4 nodes

        // batched independent loads: 4 feat float4 + 4 ntype
        float4 f[4];
        int    ty[4];
        #pragma unroll
        for (int k = 0; k < 4; k++) {
            int node = base + k;
            if (node < NN) {
                f[k]  = *(const float4*)(feat + (size_t)node * HD + lane * 4);
                ty[k] = ntype[node];
            }
        }

        float4 al = *(const float4*)(attn_l + lane * 4);
        float4 ar = *(const float4*)(attn_r + lane * 4);

        #pragma unroll
        for (int k = 0; k < 4; k++) {
            int node = base + k;
            if (node >= NN) break;
            float4 c = *(const float4*)(fc + (size_t)ty[k] * HD + lane * 4);
            float4 v;
            v.x = f[k].x * c.x; v.y = f[k].y * c.y;
            v.z = f[k].z * c.z; v.w = f[k].w * c.w;

            __half2 h0 = __floats2half2_rn(v.x, v.y);
            __half2 h1 = __floats2half2_rn(v.z, v.w);
            uint2 pack;
            pack.x = *(unsigned*)&h0;
            pack.y = *(unsigned*)&h1;
            g_fsh[(size_t)node * 32 + lane] = pack;

            float pl = v.x * al.x + v.y * al.y + v.z * al.z + v.w * al.w;
            float pr = v.x * ar.x + v.y * ar.y + v.z * ar.z + v.w * ar.w;
            // reduce within each 8-lane head group
            #pragma unroll
            for (int o = 4; o > 0; o >>= 1) {
                pl += __shfl_xor_sync(0xffffffffu, pl, o);
                pr += __shfl_xor_sync(0xffffffffu, pr, o);
            }
            if ((lane & 7) == 0) {
                int h = lane >> 3;
                g_el[node * HH + h] = pl;
                g_er[node * HH + h] = pr;
            }
        }
    } else if (blk < NBLK4 + HBLK2) {
        // 256 threads x 4 edges = 1024 edges per block
        int e0 = ((blk - NBLK4) * 256 + tid) * 4;
        if (e0 + 3 < EE) {
            int4 d4 = *(const int4*)(dst + e0);
            atomicAdd(&g_cnt[d4.x], 1);
            atomicAdd(&g_cnt[d4.y], 1);
            atomicAdd(&g_cnt[d4.z], 1);
            atomicAdd(&g_cnt[d4.w], 1);
        } else {
            for (int e = e0; e < EE; e++) atomicAdd(&g_cnt[dst[e]], 1);
        }
    } else {
        if (tid < 32) {
            int et = tid >> 2;
            int h  = tid & 3;
            const float* em = edge_emb + et * EFD;
            float acc = 0.0f;
            for (int f = 0; f < EFD; f++) {
                const float* w = W_e + (h * EFD + f) * EFD;
                float dot = 0.0f;
                #pragma unroll 8
                for (int k = 0; k < EFD; k++) dot += em[k] * w[k];
                acc += dot * attn_e[h * EFD + f];
            }
            g_ee[et * HH + h] = acc;
        } else if (tid == 32) {
            g_total = 0;
        }
    }
}

// ---------------------------------------------------------------------------
// Kernel 1: segment allocation. Block-local inclusive scan of 256 degree
// counts, then ONE atomicAdd on g_total gives the block's base. Segment order
// across blocks is nondeterministic, which is fine (per-node segments are
// contiguous; results don't depend on order). Also zeroes g_cnt for reuse.
// ---------------------------------------------------------------------------
__global__ void scan_kernel() {
    __shared__ int sh[SCAN_T];
    __shared__ int sh_base;
    int t = threadIdx.x;
    int i = blockIdx.x * SCAN_T + t;
    int v = (i < NN) ? g_cnt[i] : 0;
    sh[t] = v;
    __syncthreads();
    for (int off = 1; off < SCAN_T; off <<= 1) {
        int add = (t >= off) ? sh[t - off] : 0;
        __syncthreads();
        sh[t] += add;
        __syncthreads();
    }
    if (t == SCAN_T - 1) sh_base = atomicAdd(&g_total, sh[t]);
    __syncthreads();
    if (i < NN) {
        int o = sh_base + sh[t] - v;
        g_off[i] = o;
        g_cur[i] = o;
        g_cnt[i] = 0;                 // reset for next pipeline call
    }
}

// ---------------------------------------------------------------------------
// Kernel 2: scatter edges into CSR order. g_cur ends at CSR end offsets.
// ---------------------------------------------------------------------------
__global__ void scatter_kernel(const int* __restrict__ src,
                               const int* __restrict__ dst,
                               const int* __restrict__ efeat) {
    int e = blockIdx.x * blockDim.x + threadIdx.x;
    if (e >= EE) return;
    int d   = dst[e];
    int pos = atomicAdd(&g_cur[d], 1);
    g_edges[pos] = make_uint2((unsigned)e,
                              (unsigned)src[e] | ((unsigned)efeat[e] << 24));
}

// ---------------------------------------------------------------------------
// Kernel 3: one warp per dst node. Fused: score -> exp -> segment sum ->
// normalized attention (a_out) -> weighted fp16 fs[src] aggregation ->
// residual -> coalesced store. No atomics. Fast path for deg <= 32 keeps
// ex in registers (most nodes: mean degree 16).
// Lane layout for aggregation: lane l owns head (l>>3), dims 4*(l&7)..+3.
// ---------------------------------------------------------------------------
__global__ void __launch_bounds__(256, 5)
dst_kernel(const float* __restrict__ feat,
           float* __restrict__ rst,
           float* __restrict__ a_out) {
    __shared__ float sh_ex[8][128];            // per-warp staged ex (32 edges x 4 heads)

    int w    = (blockIdx.x * blockDim.x + threadIdx.x) >> 5;  // node id
    int wloc = threadIdx.x >> 5;
    int lane = threadIdx.x & 31;
    if (w >= NN) return;

    int start = g_off[w];
    int end   = g_cur[w];
    int deg   = end - start;

    int hsel = lane >> 3;                      // head owned for aggregation

    float4 er4 = *(const float4*)(g_er + (size_t)w * HH);

    float4 sacc = make_float4(0.f, 0.f, 0.f, 0.f);
    float a0 = 0.f, a1 = 0.f, a2 = 0.f, a3 = 0.f;

    // saved for the single-chunk fast path (deg <= 32)
    float4 ex_save = make_float4(0.f, 0.f, 0.f, 0.f);
    int    e_save  = -1;

    for (int base = 0; base < deg; base += 32) {
        int n = deg - base; if (n > 32) n = 32;

        float4 ex = make_float4(0.f, 0.f, 0.f, 0.f);
        int e = -1;
        unsigned pk = 0;

        if (lane < n) {
            int idx = start + base + lane;
            uint2 ed = g_edges[idx];
            e  = (int)ed.x;
            pk = ed.y;
            int sidx = (int)(pk & 0xFFFFFFu);
            int t    = (int)(pk >> 24);

            float4 el4 = *(const float4*)(g_el + (size_t)sidx * HH);
            float4 ee4 = *(const float4*)(g_ee + t * HH);

            float x0 = el4.x + er4.x + ee4.x;
            float x1 = el4.y + er4.y + ee4.y;
            float x2 = el4.z + er4.z + ee4.z;
            float x3 = el4.w + er4.w + ee4.w;
            x0 = (x0 > 0.f) ? x0 : NEG_SLOPE * x0;
            x1 = (x1 > 0.f) ? x1 : NEG_SLOPE * x1;
            x2 = (x2 > 0.f) ? x2 : NEG_SLOPE * x2;
            x3 = (x3 > 0.f) ? x3 : NEG_SLOPE * x3;
            ex.x = __expf(x0);
            ex.y = __expf(x1);
            ex.z = __expf(x2);
            ex.w = __expf(x3);

            sacc.x += ex.x; sacc.y += ex.y; sacc.z += ex.z; sacc.w += ex.w;

            *(float4*)(&sh_ex[wloc][lane * 4]) = ex;

            if (deg > 32) {
                // staging: will be normalized in a second sweep
                *(float4*)(a_out + (size_t)e * HH) = ex;
            }
        }
        __syncwarp();
        ex_save = ex;
        e_save  = e;

        int sidx_l = (int)(pk & 0xFFFFFFu);
        const float* exrow = &sh_ex[wloc][hsel];
        #pragma unroll 8
        for (int j = 0; j < n; j++) {
            float c  = exrow[j * 4];                       // ex_j[my head]
            int   sj = __shfl_sync(0xffffffffu, sidx_l, j);
            uint2 v  = g_fsh[(size_t)sj * 32 + lane];      // 4 halves: my head, my 4 dims
            float2 p0 = __half22float2(*(__half2*)&v.x);
            float2 p1 = __half22float2(*(__half2*)&v.y);
            a0 += c * p0.x;
            a1 += c * p0.y;
            a2 += c * p1.x;
            a3 += c * p1.y;
        }
        __syncwarp();
    }

    // reduce softmax denominators across the warp
    #pragma unroll
    for (int o = 16; o > 0; o >>= 1) {
        sacc.x += __shfl_xor_sync(0xffffffffu, sacc.x, o);
        sacc.y += __shfl_xor_sync(0xffffffffu, sacc.y, o);
        sacc.z += __shfl_xor_sync(0xffffffffu, sacc.z, o);
        sacc.w += __shfl_xor_sync(0xffffffffu, sacc.w, o);
    }
    float4 inv;
    inv.x = (sacc.x != 0.f) ? 1.f / sacc.x : 0.f;
    inv.y = (sacc.y != 0.f) ? 1.f / sacc.y : 0.f;
    inv.z = (sacc.z != 0.f) ? 1.f / sacc.z : 0.f;
    inv.w = (sacc.w != 0.f) ? 1.f / sacc.w : 0.f;

    // write normalized attention
    if (deg <= 32) {
        if (e_save >= 0) {
            float4 av;
            av.x = ex_save.x * inv.x;
            av.y = ex_save.y * inv.y;
            av.z = ex_save.z * inv.z;
            av.w = ex_save.w * inv.w;
            *(float4*)(a_out + (size_t)e_save * HH) = av;
        }
    } else {
        for (int i = start + lane; i < end; i += 32) {
            int e = (int)g_edges[i].x;
            float4 v = *(float4*)(a_out + (size_t)e * HH);
            v.x *= inv.x; v.y *= inv.y; v.z *= inv.z; v.w *= inv.w;
            *(float4*)(a_out + (size_t)e * HH) = v;
        }
    }

    // my head's inverse denominator
    float invh = (hsel == 0) ? inv.x : (hsel == 1) ? inv.y : (hsel == 2) ? inv.z : inv.w;

    // residual + output: lane l writes float4 at node*128 + l*4 (coalesced)
    size_t b = (size_t)w * HD + lane * 4;
    float4 fv = *(const float4*)(feat + b);
    float4 ov;
    ov.x = fv.x + a0 * invh;
    ov.y = fv.y + a1 * invh;
    ov.z = fv.z + a2 * invh;
    ov.w = fv.w + a3 * invh;
    *(float4*)(rst + b) = ov;
}

// ---------------------------------------------------------------------------
extern "C" void kernel_launch(void* const* d_in, const int* in_sizes, int n_in,
                              void* d_out, int out_size) {
    const float* feat     = (const float*)d_in[0];
    const float* fc       = (const float*)d_in[1];
    const float* edge_emb = (const float*)d_in[2];
    const float* W_e      = (const float*)d_in[3];
    const float* attn_l   = (const float*)d_in[4];
    const float* attn_r   = (const float*)d_in[5];
    const float* attn_e   = (const float*)d_in[6];
    const int*   ntype    = (const int*)d_in[7];
    const int*   efeat    = (const int*)d_in[8];
    const int*   src      = (const int*)d_in[9];
    const int*   dst      = (const int*)d_in[10];

    float* rst   = (float*)d_out;                       // [N, H, D]
    float* a_out = (float*)d_out + (size_t)NN * HD;     // [E, H, 1]

    prep_kernel<<<NBLK4 + HBLK2 + 1, 256>>>(feat, fc, attn_l, attn_r, ntype,
                                            dst, edge_emb, W_e, attn_e);
    scan_kernel<<<SCAN_B, SCAN_T>>>();
    {
        int threads = 256;
        int blocks = (EE + threads - 1) / threads;
        scatter_kernel<<<blocks, threads>>>(src, dst, efeat);
    }
    {
        int threads = 256;                    // 8 warps = 8 nodes per block
        int blocks = (NN + 8 - 1) / 8;
        dst_kernel<<<blocks, threads>>>(feat, rst, a_out);
    }
}

// round 11
// speedup vs baseline: 1.6571x; 1.0639x over previous
#include <cuda_runtime.h>
#include <cuda_fp16.h>

// Problem constants (fixed by the dataset)
#define NN  100000     // nodes
#define EE  1600000    // edges
#define HH  4          // heads
#define DD  32         // dim per head
#define HD  128        // H*D
#define EFD 32         // edge feat dim
#define ETN 8          // edge types
#define NEG_SLOPE 0.2f

#define SCAN_T 256
#define SCAN_B ((NN + SCAN_T - 1) / SCAN_T)   // 391
#define NBLK4  ((NN + 31) / 32)               // node blocks: 8 warps x 4 nodes
#define HBLK2  ((EE + 1023) / 1024)           // hist blocks: 256 thr x 4 edges

// Scratch (device globals — zero-initialized at module load; no allocation)
__device__ uint2    g_fsh[(size_t)NN * 32];  // fs in fp16, [node][h][d], 4 halves/lane
__device__ float    g_el[(size_t)NN * HH];
__device__ float    g_er[(size_t)NN * HH];
__device__ float    g_ee[ETN * HH];
__device__ int      g_cnt[NN];               // per-dst degree (zeroed by scan_kernel)
__device__ int      g_off[NN];               // CSR start offsets
__device__ int      g_cur[NN];               // scatter cursors -> CSR end offsets
__device__ int      g_total;                 // CSR allocation counter
__device__ uint2    g_edges[EE];             // {edge id, src|(etype<<24)} in CSR order

// ---------------------------------------------------------------------------
// Kernel 0 (fused prep), 256 threads/block:
//   blocks [0, NBLK4):   node pass, one warp per 4 nodes, batched float4
//     loads (MLP=4 per thread). lane l owns dims [4l,4l+4) = head (l>>3).
//   blocks [NBLK4, NBLK4+HBLK2): dst histogram (4 edges/thread via int4)
//   last block:          ee[t,h] (32 threads) + reset g_total
// ---------------------------------------------------------------------------
__global__ void prep_kernel(const float* __restrict__ feat,
                            const float* __restrict__ fc,
                            const float* __restrict__ attn_l,
                            const float* __restrict__ attn_r,
                            const int*   __restrict__ ntype,
                            const int*   __restrict__ dst,
                            const float* __restrict__ edge_emb,
                            const float* __restrict__ W_e,
                            const float* __restrict__ attn_e) {
    int blk = blockIdx.x;
    int tid = threadIdx.x;            // 0..255

    if (blk < NBLK4) {
        int lane = tid & 31;
        int base = blk * 32 + (tid >> 5) * 4;   // first of this warp's 4 nodes

        // batched independent loads: 4 feat float4 + 4 ntype
        float4 f[4];
        int    ty[4];
        #pragma unroll
        for (int k = 0; k < 4; k++) {
            int node = base + k;
            if (node < NN) {
                f[k]  = *(const float4*)(feat + (size_t)node * HD + lane * 4);
                ty[k] = ntype[node];
            }
        }

        float4 al = *(const float4*)(attn_l + lane * 4);
        float4 ar = *(const float4*)(attn_r + lane * 4);

        #pragma unroll
        for (int k = 0; k < 4; k++) {
            int node = base + k;
            if (node >= NN) break;
            float4 c = *(const float4*)(fc + (size_t)ty[k] * HD + lane * 4);
            float4 v;
            v.x = f[k].x * c.x; v.y = f[k].y * c.y;
            v.z = f[k].z * c.z; v.w = f[k].w * c.w;

            __half2 h0 = __floats2half2_rn(v.x, v.y);
            __half2 h1 = __floats2half2_rn(v.z, v.w);
            uint2 pack;
            pack.x = *(unsigned*)&h0;
            pack.y = *(unsigned*)&h1;
            g_fsh[(size_t)node * 32 + lane] = pack;

            float pl = v.x * al.x + v.y * al.y + v.z * al.z + v.w * al.w;
            float pr = v.x * ar.x + v.y * ar.y + v.z * ar.z + v.w * ar.w;
            // reduce within each 8-lane head group
            #pragma unroll
            for (int o = 4; o > 0; o >>= 1) {
                pl += __shfl_xor_sync(0xffffffffu, pl, o);
                pr += __shfl_xor_sync(0xffffffffu, pr, o);
            }
            if ((lane & 7) == 0) {
                int h = lane >> 3;
                g_el[node * HH + h] = pl;
                g_er[node * HH + h] = pr;
            }
        }
    } else if (blk < NBLK4 + HBLK2) {
        // 256 threads x 4 edges = 1024 edges per block
        int e0 = ((blk - NBLK4) * 256 + tid) * 4;
        if (e0 + 3 < EE) {
            int4 d4 = *(const int4*)(dst + e0);
            atomicAdd(&g_cnt[d4.x], 1);
            atomicAdd(&g_cnt[d4.y], 1);
            atomicAdd(&g_cnt[d4.z], 1);
            atomicAdd(&g_cnt[d4.w], 1);
        } else {
            for (int e = e0; e < EE; e++) atomicAdd(&g_cnt[dst[e]], 1);
        }
    } else {
        if (tid < 32) {
            int et = tid >> 2;
            int h  = tid & 3;
            const float* em = edge_emb + et * EFD;
            float acc = 0.0f;
            for (int f = 0; f < EFD; f++) {
                const float* w = W_e + (h * EFD + f) * EFD;
                float dot = 0.0f;
                #pragma unroll 8
                for (int k = 0; k < EFD; k++) dot += em[k] * w[k];
                acc += dot * attn_e[h * EFD + f];
            }
            g_ee[et * HH + h] = acc;
        } else if (tid == 32) {
            g_total = 0;
        }
    }
}

// ---------------------------------------------------------------------------
// Kernel 1: segment allocation. Block-local inclusive scan of 256 degree
// counts, then ONE atomicAdd on g_total gives the block's base. Segment order
// across blocks is nondeterministic, which is fine (per-node segments are
// contiguous; results don't depend on order). Also zeroes g_cnt for reuse.
// ---------------------------------------------------------------------------
__global__ void scan_kernel() {
    __shared__ int sh[SCAN_T];
    __shared__ int sh_base;
    int t = threadIdx.x;
    int i = blockIdx.x * SCAN_T + t;
    int v = (i < NN) ? g_cnt[i] : 0;
    sh[t] = v;
    __syncthreads();
    for (int off = 1; off < SCAN_T; off <<= 1) {
        int add = (t >= off) ? sh[t - off] : 0;
        __syncthreads();
        sh[t] += add;
        __syncthreads();
    }
    if (t == SCAN_T - 1) sh_base = atomicAdd(&g_total, sh[t]);
    __syncthreads();
    if (i < NN) {
        int o = sh_base + sh[t] - v;
        g_off[i] = o;
        g_cur[i] = o;
        g_cnt[i] = 0;                 // reset for next pipeline call
    }
}

// ---------------------------------------------------------------------------
// Kernel 2: scatter edges into CSR order, 4 edges per thread via int4 loads.
// g_cur ends at CSR end offsets.
// ---------------------------------------------------------------------------
__device__ __forceinline__ void scatter_one(int e, int s, int d, int t) {
    int pos = atomicAdd(&g_cur[d], 1);
    g_edges[pos] = make_uint2((unsigned)e,
                              (unsigned)s | ((unsigned)t << 24));
}

__global__ void scatter_kernel(const int* __restrict__ src,
                               const int* __restrict__ dst,
                               const int* __restrict__ efeat) {
    int e0 = (blockIdx.x * blockDim.x + threadIdx.x) * 4;
    if (e0 + 3 < EE) {
        int4 s4 = *(const int4*)(src   + e0);
        int4 d4 = *(const int4*)(dst   + e0);
        int4 t4 = *(const int4*)(efeat + e0);
        scatter_one(e0 + 0, s4.x, d4.x, t4.x);
        scatter_one(e0 + 1, s4.y, d4.y, t4.y);
        scatter_one(e0 + 2, s4.z, d4.z, t4.z);
        scatter_one(e0 + 3, s4.w, d4.w, t4.w);
    } else {
        for (int e = e0; e < EE; e++)
            scatter_one(e, src[e], dst[e], efeat[e]);
    }
}

// ---------------------------------------------------------------------------
// Kernel 3: one warp per dst node. Fused: score -> exp -> segment sum ->
// normalized attention (a_out) -> weighted fp16 fs[src] aggregation ->
// residual -> coalesced store. No atomics. Fast path for deg <= 32 re-reads
// its ex from sh_ex (single chunk, never overwritten) to avoid keeping a
// float4 live across the j-loop — trims registers for 6 blocks/SM.
// Lane layout for aggregation: lane l owns head (l>>3), dims 4*(l&7)..+3.
// ---------------------------------------------------------------------------
__global__ void __launch_bounds__(256, 6)
dst_kernel(const float* __restrict__ feat,
           float* __restrict__ rst,
           float* __restrict__ a_out) {
    __shared__ float sh_ex[8][128];            // per-warp staged ex (32 edges x 4 heads)

    int w    = (blockIdx.x * blockDim.x + threadIdx.x) >> 5;  // node id
    int wloc = threadIdx.x >> 5;
    int lane = threadIdx.x & 31;
    if (w >= NN) return;

    int start = g_off[w];
    int deg   = g_cur[w] - start;

    int hsel = lane >> 3;                      // head owned for aggregation

    float4 er4 = *(const float4*)(g_er + (size_t)w * HH);

    float4 sacc = make_float4(0.f, 0.f, 0.f, 0.f);
    float a0 = 0.f, a1 = 0.f, a2 = 0.f, a3 = 0.f;

    int e_save = -1;                           // fast-path edge id (deg <= 32)

    for (int base = 0; base < deg; base += 32) {
        int n = deg - base; if (n > 32) n = 32;

        unsigned pk = 0;

        if (lane < n) {
            int idx = start + base + lane;
            uint2 ed = g_edges[idx];
            pk = ed.y;
            int sidx = (int)(pk & 0xFFFFFFu);
            int t    = (int)(pk >> 24);

            float4 el4 = *(const float4*)(g_el + (size_t)sidx * HH);
            float4 ee4 = *(const float4*)(g_ee + t * HH);

            float x0 = el4.x + er4.x + ee4.x;
            float x1 = el4.y + er4.y + ee4.y;
            float x2 = el4.z + er4.z + ee4.z;
            float x3 = el4.w + er4.w + ee4.w;
            x0 = (x0 > 0.f) ? x0 : NEG_SLOPE * x0;
            x1 = (x1 > 0.f) ? x1 : NEG_SLOPE * x1;
            x2 = (x2 > 0.f) ? x2 : NEG_SLOPE * x2;
            x3 = (x3 > 0.f) ? x3 : NEG_SLOPE * x3;

            float4 ex;
            ex.x = __expf(x0);
            ex.y = __expf(x1);
            ex.z = __expf(x2);
            ex.w = __expf(x3);

            sacc.x += ex.x; sacc.y += ex.y; sacc.z += ex.z; sacc.w += ex.w;

            *(float4*)(&sh_ex[wloc][lane * 4]) = ex;

            if (deg > 32) {
                // staging: will be normalized in a second sweep
                *(float4*)(a_out + (size_t)ed.x * HH) = ex;
            } else {
                e_save = (int)ed.x;
            }
        }
        __syncwarp();

        int sidx_l = (int)(pk & 0xFFFFFFu);
        const float* exrow = &sh_ex[wloc][hsel];
        #pragma unroll 8
        for (int j = 0; j < n; j++) {
            float c  = exrow[j * 4];                       // ex_j[my head]
            int   sj = __shfl_sync(0xffffffffu, sidx_l, j);
            uint2 v  = g_fsh[(size_t)sj * 32 + lane];      // 4 halves: my head, my 4 dims
            float2 p0 = __half22float2(*(__half2*)&v.x);
            float2 p1 = __half22float2(*(__half2*)&v.y);
            a0 += c * p0.x;
            a1 += c * p0.y;
            a2 += c * p1.x;
            a3 += c * p1.y;
        }
        __syncwarp();
    }

    // reduce softmax denominators across the warp
    #pragma unroll
    for (int o = 16; o > 0; o >>= 1) {
        sacc.x += __shfl_xor_sync(0xffffffffu, sacc.x, o);
        sacc.y += __shfl_xor_sync(0xffffffffu, sacc.y, o);
        sacc.z += __shfl_xor_sync(0xffffffffu, sacc.z, o);
        sacc.w += __shfl_xor_sync(0xffffffffu, sacc.w, o);
    }
    float4 inv;
    inv.x = (sacc.x != 0.f) ? 1.f / sacc.x : 0.f;
    inv.y = (sacc.y != 0.f) ? 1.f / sacc.y : 0.f;
    inv.z = (sacc.z != 0.f) ? 1.f / sacc.z : 0.f;
    inv.w = (sacc.w != 0.f) ? 1.f / sacc.w : 0.f;

    // write normalized attention
    if (deg <= 32) {
        if (e_save >= 0) {
            float4 av = *(const float4*)(&sh_ex[wloc][lane * 4]);
            av.x *= inv.x; av.y *= inv.y; av.z *= inv.z; av.w *= inv.w;
            *(float4*)(a_out + (size_t)e_save * HH) = av;
        }
    } else {
        int end = start + deg;
        for (int i = start + lane; i < end; i += 32) {
            int e = (int)g_edges[i].x;
            float4 v = *(float4*)(a_out + (size_t)e * HH);
            v.x *= inv.x; v.y *= inv.y; v.z *= inv.z; v.w *= inv.w;
            *(float4*)(a_out + (size_t)e * HH) = v;
        }
    }

    // my head's inverse denominator
    float invh = (hsel == 0) ? inv.x : (hsel == 1) ? inv.y : (hsel == 2) ? inv.z : inv.w;

    // residual + output: lane l writes float4 at node*128 + l*4 (coalesced)
    size_t b = (size_t)w * HD + lane * 4;
    float4 fv = *(const float4*)(feat + b);
    float4 ov;
    ov.x = fv.x + a0 * invh;
    ov.y = fv.y + a1 * invh;
    ov.z = fv.z + a2 * invh;
    ov.w = fv.w + a3 * invh;
    *(float4*)(rst + b) = ov;
}

// ---------------------------------------------------------------------------
extern "C" void kernel_launch(void* const* d_in, const int* in_sizes, int n_in,
                              void* d_out, int out_size) {
    const float* feat     = (const float*)d_in[0];
    const float* fc       = (const float*)d_in[1];
    const float* edge_emb = (const float*)d_in[2];
    const float* W_e      = (const float*)d_in[3];
    const float* attn_l   = (const float*)d_in[4];
    const float* attn_r   = (const float*)d_in[5];
    const float* attn_e   = (const float*)d_in[6];
    const int*   ntype    = (const int*)d_in[7];
    const int*   efeat    = (const int*)d_in[8];
    const int*   src      = (const int*)d_in[9];
    const int*   dst      = (const int*)d_in[10];

    float* rst   = (float*)d_out;                       // [N, H, D]
    float* a_out = (float*)d_out + (size_t)NN * HD;     // [E, H, 1]

    prep_kernel<<<NBLK4 + HBLK2 + 1, 256>>>(feat, fc, attn_l, attn_r, ntype,
                                            dst, edge_emb, W_e, attn_e);
    scan_kernel<<<SCAN_B, SCAN_T>>>();
    {
        int threads = 256;                    // 4 edges per thread
        int blocks = (EE / 4 + threads - 1) / threads;
        scatter_kernel<<<blocks, threads>>>(src, dst, efeat);
    }
    {
        int threads = 256;                    // 8 warps = 8 nodes per block
        int blocks = (NN + 8 - 1) / 8;
        dst_kernel<<<blocks, threads>>>(feat, rst, a_out);
    }
}